// round 1
// baseline (speedup 1.0000x reference)
#include <cuda_runtime.h>
#include <cuda_fp16.h>
#include <math.h>

#define NNODE 100000
#define NEDGE 1600000
#define NCRYS 2000

// ---------------- static device scratch (no allocs allowed) ----------------
__device__ __align__(16) float   d_x[NNODE * 64];          // node features (fp32)
__device__ __align__(16) __half2 d_Y1h[NNODE * 64];        // x@Wf_a, pairs (c, c+64)
__device__ __align__(16) __half2 d_Y2h[NNODE * 64];        // x@Wf_b, pairs (c, c+64)
__device__ __align__(16) float2  d_zp[(size_t)NEDGE * 64]; // z pairs (col c, col c+64)
__device__ __align__(16) float   d_acc[NNODE * 64];        // message accumulator
__device__ float  d_deg[NNODE];
__device__ double d_s[128], d_ss[128];                     // edge BN stats
__device__ float  d_a1[128], d_b1[128];                    // fused BN1: z*a+b
__device__ double d_ns[64], d_nss[64];                     // node BN stats
__device__ float  d_a2[64], d_b2[64];                      // fused BN2
__device__ __align__(16) float d_csum[NCRYS * 64];
__device__ float  d_ccnt[NCRYS];

// ---------------- helpers ----------------
static __device__ __forceinline__ unsigned long long pk2(float lo, float hi) {
    unsigned long long r;
    asm("mov.b64 %0, {%1,%2};" : "=l"(r) : "f"(lo), "f"(hi));
    return r;
}
static __device__ __forceinline__ float2 upk2(unsigned long long v) {
    float2 r;
    asm("mov.b64 {%0,%1}, %2;" : "=f"(r.x), "=f"(r.y) : "l"(v));
    return r;
}
static __device__ __forceinline__ unsigned long long ffma2(unsigned long long a, unsigned long long b, unsigned long long c) {
    unsigned long long d;
    asm("fma.rn.f32x2 %0, %1, %2, %3;" : "=l"(d) : "l"(a), "l"(b), "l"(c));
    return d;
}
__device__ __forceinline__ float sp_(float v) {  // softplus, stable
    return fmaxf(v, 0.f) + log1pf(__expf(-fabsf(v)));
}
__device__ __forceinline__ float sg_(float v) {  // sigmoid
    return 1.f / (1.f + __expf(-v));
}

// ---------------- kernels ----------------
__global__ void k_zero_once() {
    int i = blockIdx.x * blockDim.x + threadIdx.x;
    int stride = gridDim.x * blockDim.x;
    for (; i < NCRYS * 64; i += stride) {
        d_csum[i] = 0.f;
        if (i < NNODE) d_deg[i] = 0.f;
        if (i < NCRYS) d_ccnt[i] = 0.f;
    }
}

__global__ void k_zero_layer(int N) {
    int i = blockIdx.x * blockDim.x + threadIdx.x;
    int stride = gridDim.x * blockDim.x;
    for (; i < N * 64; i += stride) {
        d_acc[i] = 0.f;
        if (i < 128) { d_s[i] = 0.0; d_ss[i] = 0.0; }
        if (i < 64)  { d_ns[i] = 0.0; d_nss[i] = 0.0; }
    }
}

__global__ void k_embed(const int* __restrict__ node_fea, const float* __restrict__ emb, int N) {
    int i = blockIdx.x * blockDim.x + threadIdx.x;
    if (i < N * 64) {
        int n = i >> 6, c = i & 63;
        d_x[i] = emb[node_fea[n] * 64 + c];
    }
}

__global__ void k_deg(const int* __restrict__ idx1, int E) {
    int e = blockIdx.x * blockDim.x + threadIdx.x;
    if (e < E) atomicAdd(&d_deg[idx1[e]], 1.0f);
}

// Y1 = x @ Wf[l][0:64,:],  Y2 = x @ Wf[l][64:128,:]   -> fp16 pairs (c, c+64)
__global__ void k_nodegemm(const float* __restrict__ Wf, int l, int N) {
    const int NB = 32;
    __shared__ float xs[NB][64];
    __shared__ float outs[NB][256];
    int n0 = blockIdx.x * NB;
    int t = threadIdx.x;

    for (int idx = t; idx < NB * 64; idx += 256) {
        int m = idx >> 6, k = idx & 63;
        xs[m][k] = (n0 + m < N) ? d_x[(size_t)(n0 + m) * 64 + k] : 0.f;
    }
    __syncthreads();

    int part = t >> 7;       // 0 -> Y1, 1 -> Y2
    int j = t & 127;         // output column
    const float* wbase = Wf + (size_t)(l * 169 + part * 64) * 128 + j;
    float Wreg[64];
#pragma unroll
    for (int k = 0; k < 64; k++) Wreg[k] = wbase[(size_t)k * 128];

    for (int m = 0; m < NB; m++) {
        float a = 0.f;
#pragma unroll
        for (int k = 0; k < 64; k++) a += xs[m][k] * Wreg[k];
        outs[m][t] = a;
    }
    __syncthreads();

    for (int idx = t; idx < NB * 128; idx += 256) {
        int m = idx >> 7, r = idx & 127;
        int mat = r >> 6, cp = r & 63;
        int n = n0 + m;
        if (n < N) {
            float lo = outs[m][mat * 128 + cp];
            float hi = outs[m][mat * 128 + cp + 64];
            __half2 v = __floats2half2_rn(lo, hi);
            if (mat) d_Y2h[(size_t)n * 64 + cp] = v;
            else     d_Y1h[(size_t)n * 64 + cp] = v;
        }
    }
}

// pass 1: z = Y1[i1] + Y2[i2] + ef@Wf_e + bf ; store z pairs ; accumulate stats
__global__ void k_edge1(const float* __restrict__ edge_fea,
                        const int* __restrict__ idx1, const int* __restrict__ idx2,
                        const float* __restrict__ Wf, const float* __restrict__ bf,
                        int l, int E) {
    const int EB = 128;
    __shared__ unsigned long long efp[EB][41];  // duplicated pairs (v, v)
    __shared__ int si1[EB], si2[EB];

    int e0 = blockIdx.x * EB;
    int t = threadIdx.x;

    for (int idx = t; idx < EB * 41; idx += 128) {
        int el = idx / 41, k = idx - el * 41;
        int e = e0 + el;
        float v = (e < E) ? __ldcs(&edge_fea[(size_t)e * 41 + k]) : 0.f;
        efp[el][k] = pk2(v, v);
    }
    if (t < EB) {
        int e = e0 + t;
        si1[t] = (e < E) ? idx1[e] : 0;
        si2[t] = (e < E) ? idx2[e] : 0;
    }
    __syncthreads();

    int c = t & 63;     // column pair (c, c+64)
    int h = t >> 6;     // edge-parity half
    const float* wbase = Wf + (size_t)(l * 169 + 128) * 128;
    unsigned long long Wp[41];
#pragma unroll
    for (int k = 0; k < 41; k++)
        Wp[k] = pk2(wbase[k * 128 + c], wbase[k * 128 + c + 64]);
    float bflo = bf[l * 128 + c], bfhi = bf[l * 128 + c + 64];

    float sx = 0.f, sy = 0.f, qx = 0.f, qy = 0.f;
    for (int i = h; i < EB; i += 2) {
        int e = e0 + i;
        if (e >= E) break;
        int a1 = si1[i], a2 = si2[i];
        float2 f1 = __half22float2(d_Y1h[(size_t)a1 * 64 + c]);
        float2 f2 = __half22float2(d_Y2h[(size_t)a2 * 64 + c]);
        unsigned long long acc = pk2(f1.x + f2.x + bflo, f1.y + f2.y + bfhi);
#pragma unroll
        for (int k = 0; k < 41; k++) acc = ffma2(efp[i][k], Wp[k], acc);
        float2 av = upk2(acc);
        __stcs(&d_zp[(size_t)e * 64 + c], av);
        sx += av.x; sy += av.y;
        qx += av.x * av.x; qy += av.y * av.y;
    }
    atomicAdd(&d_s[c], (double)sx);
    atomicAdd(&d_s[c + 64], (double)sy);
    atomicAdd(&d_ss[c], (double)qx);
    atomicAdd(&d_ss[c + 64], (double)qy);
}

__global__ void k_fin1(const float* __restrict__ g1, const float* __restrict__ be1, int l, int E) {
    int c = threadIdx.x;  // 128
    double mean = d_s[c] / (double)E;
    double var = d_ss[c] / (double)E - mean * mean;
    float rstd = (float)(1.0 / sqrt(var + 1e-5));
    float a = g1[l * 128 + c] * rstd;
    d_a1[c] = a;
    d_b1[c] = be1[l * 128 + c] - (float)mean * a;
}

// pass 2: msg = sigmoid(bn(gate)) * softplus(bn(conv)); scatter-add by idx1
__global__ void k_edge2(const int* __restrict__ idx1, int E) {
    const int CH = 128;
    int e0 = blockIdx.x * CH;
    int t = threadIdx.x;           // 256
    int c4 = t & 15;               // column quad
    int lane = t >> 4;             // 16 edge lanes

    float ag[4], bg[4], ac[4], bc[4];
#pragma unroll
    for (int u = 0; u < 4; u++) {
        ag[u] = d_a1[4 * c4 + u];      bg[u] = d_b1[4 * c4 + u];
        ac[u] = d_a1[64 + 4 * c4 + u]; bc[u] = d_b1[64 + 4 * c4 + u];
    }

    for (int it = 0; it < CH / 16; it++) {
        int e = e0 + it * 16 + lane;
        if (e >= E) break;
        const float4* zp = reinterpret_cast<const float4*>(&d_zp[(size_t)e * 64 + c4 * 4]);
        float4 q0 = __ldcs(zp);
        float4 q1 = __ldcs(zp + 1);
        float m0 = sg_(q0.x * ag[0] + bg[0]) * sp_(q0.y * ac[0] + bc[0]);
        float m1 = sg_(q0.z * ag[1] + bg[1]) * sp_(q0.w * ac[1] + bc[1]);
        float m2 = sg_(q1.x * ag[2] + bg[2]) * sp_(q1.y * ac[2] + bc[2]);
        float m3 = sg_(q1.z * ag[3] + bg[3]) * sp_(q1.w * ac[3] + bc[3]);
        int n = idx1[e];
        float* p = &d_acc[(size_t)n * 64 + c4 * 4];
        asm volatile("red.global.add.v4.f32 [%0], {%1,%2,%3,%4};"
                     :: "l"(p), "f"(m0), "f"(m1), "f"(m2), "f"(m3) : "memory");
    }
}

__global__ void k_nodestats(int N) {
    int t = threadIdx.x;       // 256
    int c = t & 63, nl = t >> 6;
    float s = 0.f, q = 0.f;
    for (int n = blockIdx.x * 4 + nl; n < N; n += gridDim.x * 4) {
        float rdeg = 1.f / fmaxf(d_deg[n], 1.f);
        float v = d_acc[(size_t)n * 64 + c] * rdeg;
        s += v; q += v * v;
    }
    atomicAdd(&d_ns[c], (double)s);
    atomicAdd(&d_nss[c], (double)q);
}

__global__ void k_fin2(const float* __restrict__ g2, const float* __restrict__ be2, int l, int N) {
    int c = threadIdx.x;  // 64
    double mean = d_ns[c] / (double)N;
    double var = d_nss[c] / (double)N - mean * mean;
    float rstd = (float)(1.0 / sqrt(var + 1e-5));
    float a = g2[l * 64 + c] * rstd;
    d_a2[c] = a;
    d_b2[c] = be2[l * 64 + c] - (float)mean * a;
}

__global__ void k_nodeupd(int N) {
    int i = blockIdx.x * blockDim.x + threadIdx.x;
    if (i < N * 64) {
        int n = i >> 6, c = i & 63;
        float rdeg = 1.f / fmaxf(d_deg[n], 1.f);
        float nv = d_acc[i] * rdeg * d_a2[c] + d_b2[c];
        d_x[i] = sp_(d_x[i] + nv);
    }
}

__global__ void k_crys(const int* __restrict__ idx3, int N) {
    int g = blockIdx.x * blockDim.x + threadIdx.x;
    if (g < N * 16) {
        int n = g >> 4, c4 = g & 15;
        int cr = idx3[n];
        float4 v = *reinterpret_cast<const float4*>(&d_x[(size_t)n * 64 + c4 * 4]);
        float* p = &d_csum[(size_t)cr * 64 + c4 * 4];
        asm volatile("red.global.add.v4.f32 [%0], {%1,%2,%3,%4};"
                     :: "l"(p), "f"(v.x), "f"(v.y), "f"(v.z), "f"(v.w) : "memory");
        if (c4 == 0) atomicAdd(&d_ccnt[cr], 1.0f);
    }
}

__global__ void k_head(const float* __restrict__ Wc, const float* __restrict__ bcv,
                       const float* __restrict__ Wo, const float* __restrict__ bo,
                       float* __restrict__ out, int C) {
    __shared__ float cs[64];
    __shared__ float r0[128], r1[128];
    int ci = blockIdx.x;
    int t = threadIdx.x;  // 128
    if (t < 64) cs[t] = d_csum[(size_t)ci * 64 + t] / fmaxf(d_ccnt[ci], 1.f);
    __syncthreads();
    float h = bcv[t];
#pragma unroll
    for (int k = 0; k < 64; k++) h += cs[k] * Wc[k * 128 + t];
    h = sp_(h);
    r0[t] = h * Wo[t * 2];
    r1[t] = h * Wo[t * 2 + 1];
    __syncthreads();
    for (int s = 64; s > 0; s >>= 1) {
        if (t < s) { r0[t] += r0[t + s]; r1[t] += r1[t + s]; }
        __syncthreads();
    }
    if (t == 0) {
        out[ci * 2 + 0] = r0[0] + bo[0];
        out[ci * 2 + 1] = r1[0] + bo[1];
    }
}

// ---------------- launch ----------------
extern "C" void kernel_launch(void* const* d_in, const int* in_sizes, int n_in,
                              void* d_out, int out_size) {
    const int*   node_fea = (const int*)d_in[0];
    const float* edge_fea = (const float*)d_in[1];
    const int*   idx1 = (const int*)d_in[2];
    const int*   idx2 = (const int*)d_in[3];
    const int*   idx3 = (const int*)d_in[4];
    const float* emb  = (const float*)d_in[5];
    const float* Wf   = (const float*)d_in[6];
    const float* bf   = (const float*)d_in[7];
    const float* g1   = (const float*)d_in[8];
    const float* be1  = (const float*)d_in[9];
    const float* g2   = (const float*)d_in[10];
    const float* be2  = (const float*)d_in[11];
    const float* Wc   = (const float*)d_in[12];
    const float* bcv  = (const float*)d_in[13];
    const float* Wo   = (const float*)d_in[14];
    const float* bo   = (const float*)d_in[15];
    float* out = (float*)d_out;

    int N = in_sizes[0];
    int E = in_sizes[2];
    int C = out_size / 2;

    k_zero_once<<<512, 256>>>();
    k_embed<<<(N * 64 + 255) / 256, 256>>>(node_fea, emb, N);
    k_deg<<<(E + 255) / 256, 256>>>(idx1, E);

    for (int l = 0; l < 3; l++) {
        k_zero_layer<<<(N * 64 + 255) / 256, 256>>>(N);
        k_nodegemm<<<(N + 31) / 32, 256>>>(Wf, l, N);
        k_edge1<<<(E + 127) / 128, 128>>>(edge_fea, idx1, idx2, Wf, bf, l, E);
        k_fin1<<<1, 128>>>(g1, be1, l, E);
        k_edge2<<<(E + 127) / 128, 256>>>(idx1, E);
        k_nodestats<<<256, 256>>>(N);
        k_fin2<<<1, 64>>>(g2, be2, l, N);
        k_nodeupd<<<(N * 64 + 255) / 256, 256>>>(N);
    }

    k_crys<<<(N * 16 + 255) / 256, 256>>>(idx3, N);
    k_head<<<C, 128>>>(Wc, bcv, Wo, bo, out, C);
}